// round 14
// baseline (speedup 1.0000x reference)
#include <cuda_runtime.h>
#include <cuda_bf16.h>
#include <cstdint>

#define B_ 4
#define N_ 4096
#define F_ 1024
#define H_ 16
#define D_ 64
#define E_ 256
#define KSPLIT 4
#define SPLIT 2

// ---- tensor-core helpers (portable sm_80+) ----
__device__ __forceinline__ uint32_t smem_u32(const void* p) {
    uint32_t a;
    asm("{ .reg .u64 t; cvta.to.shared.u64 t, %1; cvt.u32.u64 %0, t; }" : "=r"(a) : "l"(p));
    return a;
}
__device__ __forceinline__ void ldsm4(uint32_t* r, uint32_t a) {
    asm volatile("ldmatrix.sync.aligned.m8n8.x4.shared.b16 {%0,%1,%2,%3}, [%4];"
        : "=r"(r[0]), "=r"(r[1]), "=r"(r[2]), "=r"(r[3]) : "r"(a));
}
__device__ __forceinline__ void ldsm4t(uint32_t* r, uint32_t a) {
    asm volatile("ldmatrix.sync.aligned.m8n8.x4.trans.shared.b16 {%0,%1,%2,%3}, [%4];"
        : "=r"(r[0]), "=r"(r[1]), "=r"(r[2]), "=r"(r[3]) : "r"(a));
}
__device__ __forceinline__ void mma16816(float* c, const uint32_t* a, const uint32_t* b) {
    asm volatile("mma.sync.aligned.m16n8k16.row.col.f32.bf16.bf16.f32 "
        "{%0,%1,%2,%3}, {%4,%5,%6,%7}, {%8,%9}, {%0,%1,%2,%3};"
        : "+f"(c[0]), "+f"(c[1]), "+f"(c[2]), "+f"(c[3])
        : "r"(a[0]), "r"(a[1]), "r"(a[2]), "r"(a[3]), "r"(b[0]), "r"(b[1]));
}
#define CP16(dst, src) asm volatile("cp.async.cg.shared.global [%0], [%1], 16;" :: "r"(dst), "l"(src))
#define CP_COMMIT()    asm volatile("cp.async.commit_group;" ::: "memory")
#define CP_WAIT0()     asm volatile("cp.async.wait_group 0;" ::: "memory")

__device__ __forceinline__ void split1(float v, __nv_bfloat16& h, __nv_bfloat16& l) {
    h = __float2bfloat16(v);
    l = __float2bfloat16(v - __bfloat162float(h));
}
__device__ __forceinline__ uint32_t packbf(float a, float b) {
    __nv_bfloat162 t(__float2bfloat16(a), __float2bfloat16(b));
    return *(uint32_t*)&t;
}
__device__ __forceinline__ uint32_t packbf_lo(float a, float b) {
    __nv_bfloat16 ha = __float2bfloat16(a), hb = __float2bfloat16(b);
    __nv_bfloat162 t(__float2bfloat16(a - __bfloat162float(ha)),
                     __float2bfloat16(b - __bfloat162float(hb)));
    return *(uint32_t*)&t;
}

// ---- scratch ----
__device__ float g_xpp[KSPLIT*B_*E_*F_];
__device__ __nv_bfloat16 g_xh [B_*N_*F_], g_xl [B_*N_*F_];
__device__ __nv_bfloat16 g_qh [B_*N_*F_], g_ql [B_*N_*F_];
__device__ __nv_bfloat16 g_aoh[B_*N_*F_], g_aol[B_*N_*F_];
__device__ __nv_bfloat16 g_xph[B_*E_*F_], g_xpl[B_*E_*F_];
__device__ __nv_bfloat16 g_kph[B_*E_*F_], g_kpl[B_*E_*F_];
__device__ __nv_bfloat16 g_vth[B_*F_*E_], g_vtl[B_*F_*E_];
__device__ __nv_bfloat16 g_ph [N_*E_],   g_pl [N_*E_];
__device__ __nv_bfloat16 g_wqh[F_*F_], g_wql[F_*F_];
__device__ __nv_bfloat16 g_wkh[F_*F_], g_wkl[F_*F_];
__device__ __nv_bfloat16 g_wvh[F_*F_], g_wvl[F_*F_];
__device__ __nv_bfloat16 g_woh[F_*F_], g_wol[F_*F_];

// ---------------------------------------------------------------------------
// All 6 input splits in ONE launch (z: 0=x, 1=proj, 2=Wq, 3=Wk, 4=Wv, 5=Wo)
// ---------------------------------------------------------------------------
__global__ void __launch_bounds__(256)
split_all(const float* __restrict__ x, const float* __restrict__ proj,
          const float* __restrict__ w0, const float* __restrict__ w1,
          const float* __restrict__ w2, const float* __restrict__ w3)
{
    const int z = blockIdx.z;
    const float* in;
    __nv_bfloat16 *hi, *lo;
    int n4;
    switch (z) {
        case 0:  in = x;    hi = g_xh;  lo = g_xl;  n4 = B_*N_*F_/4; break;
        case 1:  in = proj; hi = g_ph;  lo = g_pl;  n4 = N_*E_/4;    break;
        case 2:  in = w0;   hi = g_wqh; lo = g_wql; n4 = F_*F_/4;    break;
        case 3:  in = w1;   hi = g_wkh; lo = g_wkl; n4 = F_*F_/4;    break;
        case 4:  in = w2;   hi = g_wvh; lo = g_wvl; n4 = F_*F_/4;    break;
        default: in = w3;   hi = g_woh; lo = g_wol; n4 = F_*F_/4;    break;
    }
    int i = blockIdx.x * 256 + threadIdx.x;
    if (i >= n4) return;
    float4 v = ((const float4*)in)[i];
    __nv_bfloat16 h0, h1, h2, h3, l0, l1, l2, l3;
    split1(v.x, h0, l0); split1(v.y, h1, l1);
    split1(v.z, h2, l2); split1(v.w, h3, l3);
    ((__nv_bfloat162*)hi)[i*2]   = __nv_bfloat162(h0, h1);
    ((__nv_bfloat162*)hi)[i*2+1] = __nv_bfloat162(h2, h3);
    ((__nv_bfloat162*)lo)[i*2]   = __nv_bfloat162(l0, l1);
    ((__nv_bfloat162*)lo)[i*2+1] = __nv_bfloat162(l2, l3);
}

#define PAD        40

// ---------------------------------------------------------------------------
// HMMA split-bf16 NT GEMM (128x128, BK=32, 2-stage, 2 CTAs/SM, 1 barrier/tile)
// ---------------------------------------------------------------------------
#define MAT_BYTES  (128 * PAD * 2)
#define STG_BYTES  (4 * MAT_BYTES)
#define TCG_SMEM   (2 * STG_BYTES)

__device__ __forceinline__ void stage_load(
    const __nv_bfloat16* __restrict__ Ah, const __nv_bfloat16* __restrict__ Al,
    const __nv_bfloat16* __restrict__ Bh, const __nv_bfloat16* __restrict__ Bl,
    int bm, int bn, int kt, uint32_t sbase, int tid)
{
    const __nv_bfloat16* gp[4] = {
        Ah + (size_t)bm * 1024, Al + (size_t)bm * 1024,
        Bh + (size_t)bn * 1024, Bl + (size_t)bn * 1024 };
#pragma unroll
    for (int m = 0; m < 4; m++) {
        const __nv_bfloat16* base = gp[m] + kt * 32;
        uint32_t sb = sbase + m * MAT_BYTES;
#pragma unroll
        for (int it = 0; it < 2; it++) {
            int c = tid + it * 256;
            int row = c >> 2, q = c & 3;
            CP16(sb + row * (PAD * 2) + q * 16, base + (size_t)row * 1024 + q * 8);
        }
    }
}

__global__ void __launch_bounds__(256, 2)
tc_gemm(const __nv_bfloat16* __restrict__ Ah, const __nv_bfloat16* __restrict__ Al,
        const __nv_bfloat16* __restrict__ Bh0, const __nv_bfloat16* __restrict__ Bl0,
        const __nv_bfloat16* __restrict__ Bh1, const __nv_bfloat16* __restrict__ Bl1,
        float* Cf,
        __nv_bfloat16* Ch0, __nv_bfloat16* Cl0,
        __nv_bfloat16* Ch1, __nv_bfloat16* Cl1,
        int mode0, int mode1, float scale)
{
    const __nv_bfloat16* Bh = blockIdx.z ? Bh1 : Bh0;
    const __nv_bfloat16* Bl = blockIdx.z ? Bl1 : Bl0;
    __nv_bfloat16* Ch = blockIdx.z ? Ch1 : Ch0;
    __nv_bfloat16* Cl = blockIdx.z ? Cl1 : Cl0;
    const int mode = blockIdx.z ? mode1 : mode0;

    extern __shared__ __nv_bfloat16 smb[];
    const uint32_t sb = smem_u32(smb);
    const int tid  = threadIdx.x;
    const int lane = tid & 31;
    const int wid  = tid >> 5;
    const int bn   = blockIdx.x * 128;
    const int bm   = blockIdx.y * 128;
    const int wm   = (wid >> 2) * 64;
    const int wn   = (wid & 3) * 32;

    float acc[4][4][4];
#pragma unroll
    for (int i = 0; i < 4; i++)
#pragma unroll
        for (int j = 0; j < 4; j++)
#pragma unroll
            for (int v = 0; v < 4; v++) acc[i][j][v] = 0.f;

    const int lmA = lane & 15;
    const int lkA = (lane >> 4) * 16;
    const int rB  = (lane & 7) + ((lane >> 4) << 3);
    const int lkB = ((lane >> 3) & 1) * 16;

    stage_load(Ah, Al, Bh, Bl, bm, bn, 0, sb, tid);
    CP_COMMIT();

#pragma unroll 1
    for (int kt = 0; kt < 32; kt++) {
        CP_WAIT0();
        __syncthreads();
        if (kt + 1 < 32) {
            stage_load(Ah, Al, Bh, Bl, bm, bn, kt + 1,
                       sb + ((kt + 1) & 1) * STG_BYTES, tid);
            CP_COMMIT();
        }

        const uint32_t st = sb + (kt & 1) * STG_BYTES;
#pragma unroll
        for (int ks = 0; ks < 2; ks++) {
            uint32_t ah[4][4], al[4][4], bh[2][4], bl[2][4];
#pragma unroll
            for (int mt = 0; mt < 4; mt++) {
                uint32_t a = st + (wm + mt * 16 + lmA) * (PAD * 2) + lkA + ks * 32;
                ldsm4(ah[mt], a);
                ldsm4(al[mt], a + MAT_BYTES);
            }
#pragma unroll
            for (int p = 0; p < 2; p++) {
                uint32_t a = st + 2 * MAT_BYTES
                           + (wn + p * 16 + rB) * (PAD * 2) + lkB + ks * 32;
                ldsm4(bh[p], a);
                ldsm4(bl[p], a + MAT_BYTES);
            }
#pragma unroll
            for (int mt = 0; mt < 4; mt++)
#pragma unroll
                for (int nt = 0; nt < 4; nt++) {
                    float* cc = acc[mt][nt];
                    const uint32_t* bhp = &bh[nt >> 1][(nt & 1) * 2];
                    const uint32_t* blp = &bl[nt >> 1][(nt & 1) * 2];
                    mma16816(cc, ah[mt], bhp);
                    mma16816(cc, ah[mt], blp);
                    mma16816(cc, al[mt], bhp);
                }
        }
    }
    __syncthreads();

    const int mr = lane >> 2, nc = (lane & 3) * 2;
#pragma unroll
    for (int mt = 0; mt < 4; mt++)
#pragma unroll
        for (int nt = 0; nt < 4; nt++) {
            int m = bm + wm + mt * 16 + mr;
            int n = bn + wn + nt * 8 + nc;
            float v00 = acc[mt][nt][0], v01 = acc[mt][nt][1];
            float v10 = acc[mt][nt][2], v11 = acc[mt][nt][3];
            if (mode == 0) {
                *(float2*)&Cf[(size_t)m * 1024 + n]       = make_float2(v00, v01);
                *(float2*)&Cf[(size_t)(m + 8) * 1024 + n] = make_float2(v10, v11);
            } else if (mode == 3) {
                int b = m >> 8, e = m & 255;
                __nv_bfloat16 h, l;
                split1(v00, h, l);
                Ch[(size_t)b*F_*E_ + (size_t)n*E_ + e] = h;
                Cl[(size_t)b*F_*E_ + (size_t)n*E_ + e] = l;
                split1(v01, h, l);
                Ch[(size_t)b*F_*E_ + (size_t)(n+1)*E_ + e] = h;
                Cl[(size_t)b*F_*E_ + (size_t)(n+1)*E_ + e] = l;
                split1(v10, h, l);
                Ch[(size_t)b*F_*E_ + (size_t)n*E_ + e + 8] = h;
                Cl[(size_t)b*F_*E_ + (size_t)n*E_ + e + 8] = l;
                split1(v11, h, l);
                Ch[(size_t)b*F_*E_ + (size_t)(n+1)*E_ + e + 8] = h;
                Cl[(size_t)b*F_*E_ + (size_t)(n+1)*E_ + e + 8] = l;
            } else {
                float s = (mode == 1) ? scale : 1.f;
                v00 *= s; v01 *= s; v10 *= s; v11 *= s;
                __nv_bfloat16 h0, l0, h1, l1;
                split1(v00, h0, l0); split1(v01, h1, l1);
                *(__nv_bfloat162*)&Ch[(size_t)m*1024 + n] = __nv_bfloat162(h0, h1);
                *(__nv_bfloat162*)&Cl[(size_t)m*1024 + n] = __nv_bfloat162(l0, l1);
                split1(v10, h0, l0); split1(v11, h1, l1);
                *(__nv_bfloat162*)&Ch[(size_t)(m+8)*1024 + n] = __nv_bfloat162(h0, h1);
                *(__nv_bfloat162*)&Cl[(size_t)(m+8)*1024 + n] = __nv_bfloat162(l0, l1);
            }
        }
}

// ---------------------------------------------------------------------------
// HMMA split-bf16 TN GEMM (trans ldmatrix): xp = proj^T @ x, split-K x4.
// ---------------------------------------------------------------------------
#define PPAD       136
#define PT_BYTES   (32 * PPAD * 2)
#define PSTG       (4 * PT_BYTES)
#define PROJ_SMEM  (2 * PSTG)

__device__ __forceinline__ void stage_load_p(
    const __nv_bfloat16* __restrict__ ph, const __nv_bfloat16* __restrict__ pl,
    const __nv_bfloat16* __restrict__ xh, const __nv_bfloat16* __restrict__ xl,
    int e0, int f0, int n0, uint32_t sbase, int tid)
{
    const __nv_bfloat16* gp[4] = {
        ph + (size_t)n0 * 256 + e0,  pl + (size_t)n0 * 256 + e0,
        xh + (size_t)n0 * 1024 + f0, xl + (size_t)n0 * 1024 + f0 };
    const int gs[4] = {256, 256, 1024, 1024};
#pragma unroll
    for (int m = 0; m < 4; m++) {
        uint32_t sb = sbase + m * PT_BYTES;
#pragma unroll
        for (int it = 0; it < 2; it++) {
            int c = tid + it * 256;
            int row = c >> 4, q = c & 15;
            CP16(sb + row * (PPAD * 2) + q * 16, gp[m] + (size_t)row * gs[m] + q * 8);
        }
    }
}

__global__ void __launch_bounds__(256, 2)
proj_tc(const __nv_bfloat16* __restrict__ ph, const __nv_bfloat16* __restrict__ pl,
        const __nv_bfloat16* __restrict__ xh, const __nv_bfloat16* __restrict__ xl)
{
    extern __shared__ __nv_bfloat16 smb[];
    const uint32_t sb = smem_u32(smb);
    const int tid  = threadIdx.x;
    const int lane = tid & 31;
    const int wid  = tid >> 5;
    const int f0   = blockIdx.x * 128;
    const int e0   = blockIdx.y * 128;
    const int b    = blockIdx.z >> 2;
    const int ksp  = blockIdx.z & 3;
    const int wm   = (wid >> 2) * 64;
    const int wn   = (wid & 3) * 32;
    const int nlo  = ksp * (N_ / KSPLIT);

    const __nv_bfloat16* xhb = xh + (size_t)b * N_ * F_;
    const __nv_bfloat16* xlb = xl + (size_t)b * N_ * F_;

    float acc[4][4][4];
#pragma unroll
    for (int i = 0; i < 4; i++)
#pragma unroll
        for (int j = 0; j < 4; j++)
#pragma unroll
            for (int v = 0; v < 4; v++) acc[i][j][v] = 0.f;

    const int krA = (lane & 7) + ((lane & 16) >> 1);
    const int mcA = lane & 8;
    const int krB = (lane & 7) + (lane & 8);
    const int fcB = (lane >> 4) << 3;

    stage_load_p(ph, pl, xhb, xlb, e0, f0, nlo, sb, tid);
    CP_COMMIT();

#pragma unroll 1
    for (int kt = 0; kt < 32; kt++) {
        CP_WAIT0();
        __syncthreads();
        if (kt + 1 < 32) {
            stage_load_p(ph, pl, xhb, xlb, e0, f0, nlo + (kt + 1) * 32,
                         sb + ((kt + 1) & 1) * PSTG, tid);
            CP_COMMIT();
        }

        const uint32_t st = sb + (kt & 1) * PSTG;
#pragma unroll
        for (int ks = 0; ks < 2; ks++) {
            uint32_t ah[4][4], al[4][4], bh[2][4], bl[2][4];
#pragma unroll
            for (int mt = 0; mt < 4; mt++) {
                uint32_t a = st + (ks * 16 + krA) * (PPAD * 2)
                           + (wm + mt * 16 + mcA) * 2;
                ldsm4t(ah[mt], a);
                ldsm4t(al[mt], a + PT_BYTES);
            }
#pragma unroll
            for (int p = 0; p < 2; p++) {
                uint32_t a = st + 2 * PT_BYTES + (ks * 16 + krB) * (PPAD * 2)
                           + (wn + p * 16 + fcB) * 2;
                ldsm4t(bh[p], a);
                ldsm4t(bl[p], a + PT_BYTES);
            }
#pragma unroll
            for (int mt = 0; mt < 4; mt++)
#pragma unroll
                for (int nt = 0; nt < 4; nt++) {
                    float* cc = acc[mt][nt];
                    const uint32_t* bhp = &bh[nt >> 1][(nt & 1) * 2];
                    const uint32_t* blp = &bl[nt >> 1][(nt & 1) * 2];
                    mma16816(cc, ah[mt], bhp);
                    mma16816(cc, ah[mt], blp);
                    mma16816(cc, al[mt], bhp);
                }
        }
    }
    __syncthreads();

    float* Cb = g_xpp + (size_t)ksp * (B_ * E_ * F_) + (size_t)b * E_ * F_;
    const int mr = lane >> 2, nc = (lane & 3) * 2;
#pragma unroll
    for (int mt = 0; mt < 4; mt++)
#pragma unroll
        for (int nt = 0; nt < 4; nt++) {
            int e = e0 + wm + mt * 16 + mr;
            int f = f0 + wn + nt * 8 + nc;
            *(float2*)&Cb[(size_t)e * F_ + f] =
                make_float2(acc[mt][nt][0], acc[mt][nt][1]);
            *(float2*)&Cb[(size_t)(e + 8) * F_ + f] =
                make_float2(acc[mt][nt][2], acc[mt][nt][3]);
        }
}

__global__ void __launch_bounds__(256)
xp_reduce()
{
    int i = blockIdx.x * 256 + threadIdx.x;
    const int tot = B_ * E_ * F_ / 4;
    if (i >= tot) return;
    const float4* p0 = (const float4*)g_xpp;
    float4 a = p0[i], b = p0[i + tot], c = p0[i + 2 * tot], d = p0[i + 3 * tot];
    float s[4] = {a.x + b.x + c.x + d.x, a.y + b.y + c.y + d.y,
                  a.z + b.z + c.z + d.z, a.w + b.w + c.w + d.w};
    __nv_bfloat16 h[4], l[4];
#pragma unroll
    for (int k = 0; k < 4; k++) split1(s[k], h[k], l[k]);
    ((__nv_bfloat162*)g_xph)[i*2]   = __nv_bfloat162(h[0], h[1]);
    ((__nv_bfloat162*)g_xph)[i*2+1] = __nv_bfloat162(h[2], h[3]);
    ((__nv_bfloat162*)g_xpl)[i*2]   = __nv_bfloat162(l[0], l[1]);
    ((__nv_bfloat162*)g_xpl)[i*2+1] = __nv_bfloat162(l[2], l[3]);
}

// ---------------------------------------------------------------------------
// Persistent HMMA flash attention (R13, unchanged).
// ---------------------------------------------------------------------------
#define KH_B   0
#define KL_B   36864
#define VTH_B  73728
#define VTL_B  107520
#define Q_B    141312
#define QBUF   36864
#define ATT_SMEM (Q_B + 2 * QBUF)
#define KROW   144
#define VROW   528

__device__ __forceinline__ void load_q_tile(
    uint32_t qbase, const __nv_bfloat16* qh, const __nv_bfloat16* ql,
    size_t row0, int tid)
{
    for (int c = tid; c < 1024; c += 256) {
        int q = c >> 3, k = c & 7;
        CP16(qbase + q * KROW + k * 16,          qh + (row0 + q) * F_ + k * 8);
        CP16(qbase + 18432 + q * KROW + k * 16,  ql + (row0 + q) * F_ + k * 8);
    }
}

__global__ void __launch_bounds__(256, 1)
attn_tc()
{
    extern __shared__ __nv_bfloat16 smb[];
    const uint32_t sb = smem_u32(smb);
    const int tid  = threadIdx.x;
    const int lane = tid & 31;
    const int wid  = tid >> 5;
    const int h    = blockIdx.y;
    const int b    = blockIdx.z;
    const int wq   = wid * 16;

    const __nv_bfloat16* qh = g_qh + (size_t)b * N_ * F_ + h * D_;
    const __nv_bfloat16* ql = g_ql + (size_t)b * N_ * F_ + h * D_;

    {
        const __nv_bfloat16* kh = g_kph + ((size_t)b*E_)*F_ + h*D_;
        const __nv_bfloat16* kl = g_kpl + ((size_t)b*E_)*F_ + h*D_;
        for (int c = tid; c < 2048; c += 256) {
            int e = c >> 3, q = c & 7;
            CP16(sb + KH_B + e*KROW + q*16, kh + (size_t)e*F_ + q*8);
            CP16(sb + KL_B + e*KROW + q*16, kl + (size_t)e*F_ + q*8);
        }
        const __nv_bfloat16* vh = g_vth + ((size_t)b*F_ + h*D_)*E_;
        const __nv_bfloat16* vl = g_vtl + ((size_t)b*F_ + h*D_)*E_;
        for (int c = tid; c < 2048; c += 256) {
            int dv = c >> 5, ch = c & 31;
            CP16(sb + VTH_B + dv*VROW + ch*16, vh + (size_t)dv*E_ + ch*8);
            CP16(sb + VTL_B + dv*VROW + ch*16, vl + (size_t)dv*E_ + ch*8);
        }
        load_q_tile(sb + Q_B, qh, ql, (size_t)blockIdx.x * 128, tid);
    }
    CP_COMMIT();
    CP_WAIT0();
    __syncthreads();

    const int lmA = lane & 15;
    const int lkA = (lane >> 4) * 16;
    const int rB  = (lane & 7) + ((lane >> 4) << 3);
    const int lkB = ((lane >> 3) & 1) * 16;

    int qb = 0;
#pragma unroll 1
    for (int t = blockIdx.x; t < N_ / 128; t += SPLIT) {
        const uint32_t qbase = sb + Q_B + qb * QBUF;

        float sc[32][4];
#pragma unroll
        for (int tt = 0; tt < 32; tt++)
#pragma unroll
            for (int v = 0; v < 4; v++) sc[tt][v] = 0.f;

#pragma unroll
        for (int kt = 0; kt < 4; kt++) {
            uint32_t qh4[4], ql4[4];
            {
                uint32_t a = qbase + (wq + lmA) * KROW + lkA + kt * 32;
                ldsm4(qh4, a);
                ldsm4(ql4, a + 18432);
            }
#pragma unroll
            for (int eb = 0; eb < 16; eb++) {
                uint32_t bh4[4], bl4[4];
                uint32_t a = sb + KH_B + (eb * 16 + rB) * KROW + lkB + kt * 32;
                ldsm4(bh4, a);
                ldsm4(bl4, a + (KL_B - KH_B));
#pragma unroll
                for (int half = 0; half < 2; half++) {
                    float* cc = sc[2 * eb + half];
                    const uint32_t* bhp = &bh4[half * 2];
                    const uint32_t* blp = &bl4[half * 2];
                    mma16816(cc, qh4, bhp);
                    mma16816(cc, qh4, blp);
                    mma16816(cc, ql4, bhp);
                }
            }
        }

        if (t + SPLIT < N_ / 128) {
            load_q_tile(sb + Q_B + (qb ^ 1) * QBUF, qh, ql,
                        (size_t)(t + SPLIT) * 128, tid);
            CP_COMMIT();
        }

        float mx0 = sc[0][0], mx1 = sc[0][2];
#pragma unroll
        for (int tt = 0; tt < 32; tt++) {
            mx0 = fmaxf(mx0, fmaxf(sc[tt][0], sc[tt][1]));
            mx1 = fmaxf(mx1, fmaxf(sc[tt][2], sc[tt][3]));
        }
        mx0 = fmaxf(mx0, __shfl_xor_sync(0xffffffffu, mx0, 1));
        mx0 = fmaxf(mx0, __shfl_xor_sync(0xffffffffu, mx0, 2));
        mx1 = fmaxf(mx1, __shfl_xor_sync(0xffffffffu, mx1, 1));
        mx1 = fmaxf(mx1, __shfl_xor_sync(0xffffffffu, mx1, 2));

        float s0 = 0.f, s1 = 0.f;
#pragma unroll
        for (int tt = 0; tt < 32; tt++) {
            sc[tt][0] = __expf(sc[tt][0] - mx0);
            sc[tt][1] = __expf(sc[tt][1] - mx0);
            sc[tt][2] = __expf(sc[tt][2] - mx1);
            sc[tt][3] = __expf(sc[tt][3] - mx1);
            s0 += sc[tt][0] + sc[tt][1];
            s1 += sc[tt][2] + sc[tt][3];
        }
        s0 += __shfl_xor_sync(0xffffffffu, s0, 1);
        s0 += __shfl_xor_sync(0xffffffffu, s0, 2);
        s1 += __shfl_xor_sync(0xffffffffu, s1, 1);
        s1 += __shfl_xor_sync(0xffffffffu, s1, 2);

        float o[8][4];
#pragma unroll
        for (int tt = 0; tt < 8; tt++)
#pragma unroll
            for (int v = 0; v < 4; v++) o[tt][v] = 0.f;

#pragma unroll
        for (int kt = 0; kt < 16; kt++) {
            uint32_t ph4[4], pl4[4];
            ph4[0] = packbf   (sc[2*kt][0],   sc[2*kt][1]);
            ph4[1] = packbf   (sc[2*kt][2],   sc[2*kt][3]);
            ph4[2] = packbf   (sc[2*kt+1][0], sc[2*kt+1][1]);
            ph4[3] = packbf   (sc[2*kt+1][2], sc[2*kt+1][3]);
            pl4[0] = packbf_lo(sc[2*kt][0],   sc[2*kt][1]);
            pl4[1] = packbf_lo(sc[2*kt][2],   sc[2*kt][3]);
            pl4[2] = packbf_lo(sc[2*kt+1][0], sc[2*kt+1][1]);
            pl4[3] = packbf_lo(sc[2*kt+1][2], sc[2*kt+1][3]);
#pragma unroll
            for (int pr = 0; pr < 4; pr++) {
                uint32_t vh4[4], vl4[4];
                uint32_t a = sb + VTH_B + (pr * 16 + rB) * VROW + lkB + kt * 32;
                ldsm4(vh4, a);
                ldsm4(vl4, a + (VTL_B - VTH_B));
#pragma unroll
                for (int half = 0; half < 2; half++) {
                    float* cc = o[2 * pr + half];
                    const uint32_t* bhp = &vh4[half * 2];
                    const uint32_t* blp = &vl4[half * 2];
                    mma16816(cc, ph4, bhp);
                    mma16816(cc, ph4, blp);
                    mma16816(cc, pl4, bhp);
                }
            }
        }

        const float inv0 = 1.f / s0, inv1 = 1.f / s1;
        const int row0 = b * N_ + t * 128 + wq + (lane >> 2);
        const int col0 = h * D_ + (lane & 3) * 2;
#pragma unroll
        for (int nt = 0; nt < 8; nt++) {
            float v00 = o[nt][0] * inv0, v01 = o[nt][1] * inv0;
            float v10 = o[nt][2] * inv1, v11 = o[nt][3] * inv1;
            __nv_bfloat16 h0, l0, h1, l1;
            size_t p0 = (size_t)row0 * F_ + col0 + nt * 8;
            split1(v00, h0, l0); split1(v01, h1, l1);
            *(__nv_bfloat162*)&g_aoh[p0] = __nv_bfloat162(h0, h1);
            *(__nv_bfloat162*)&g_aol[p0] = __nv_bfloat162(l0, l1);
            size_t p1 = (size_t)(row0 + 8) * F_ + col0 + nt * 8;
            split1(v10, h0, l0); split1(v11, h1, l1);
            *(__nv_bfloat162*)&g_aoh[p1] = __nv_bfloat162(h0, h1);
            *(__nv_bfloat162*)&g_aol[p1] = __nv_bfloat162(l0, l1);
        }

        CP_WAIT0();
        __syncthreads();
        qb ^= 1;
    }
}

// ---------------------------------------------------------------------------
extern "C" void kernel_launch(void* const* d_in, const int* in_sizes, int n_in,
                              void* d_out, int out_size)
{
    (void)in_sizes; (void)n_in; (void)out_size;
    const float* x    = (const float*)d_in[0];
    const float* proj = (const float*)d_in[1];
    const float* Wq   = (const float*)d_in[2];
    const float* Wk   = (const float*)d_in[3];
    const float* Wv   = (const float*)d_in[4];
    const float* Wo   = (const float*)d_in[5];
    float* out = (float*)d_out;

    __nv_bfloat16 *xh, *xl, *qh, *ql, *aoh, *aol, *xph, *xpl, *ph, *pl;
    __nv_bfloat16 *kph, *kpl, *vth, *vtl;
    __nv_bfloat16 *wqh, *wql, *wkh, *wkl, *wvh, *wvl, *woh, *wol;
    cudaGetSymbolAddress((void**)&xh,  g_xh);
    cudaGetSymbolAddress((void**)&xl,  g_xl);
    cudaGetSymbolAddress((void**)&qh,  g_qh);
    cudaGetSymbolAddress((void**)&ql,  g_ql);
    cudaGetSymbolAddress((void**)&aoh, g_aoh);
    cudaGetSymbolAddress((void**)&aol, g_aol);
    cudaGetSymbolAddress((void**)&xph, g_xph);
    cudaGetSymbolAddress((void**)&xpl, g_xpl);
    cudaGetSymbolAddress((void**)&kph, g_kph);
    cudaGetSymbolAddress((void**)&kpl, g_kpl);
    cudaGetSymbolAddress((void**)&vth, g_vth);
    cudaGetSymbolAddress((void**)&vtl, g_vtl);
    cudaGetSymbolAddress((void**)&ph,  g_ph);
    cudaGetSymbolAddress((void**)&pl,  g_pl);
    cudaGetSymbolAddress((void**)&wqh, g_wqh);
    cudaGetSymbolAddress((void**)&wql, g_wql);
    cudaGetSymbolAddress((void**)&wkh, g_wkh);
    cudaGetSymbolAddress((void**)&wkl, g_wkl);
    cudaGetSymbolAddress((void**)&wvh, g_wvh);
    cudaGetSymbolAddress((void**)&wvl, g_wvl);
    cudaGetSymbolAddress((void**)&woh, g_woh);
    cudaGetSymbolAddress((void**)&wol, g_wol);

    cudaFuncSetAttribute(tc_gemm,
                         cudaFuncAttributeMaxDynamicSharedMemorySize, TCG_SMEM);
    cudaFuncSetAttribute(proj_tc,
                         cudaFuncAttributeMaxDynamicSharedMemorySize, PROJ_SMEM);
    cudaFuncSetAttribute(attn_tc,
                         cudaFuncAttributeMaxDynamicSharedMemorySize, ATT_SMEM);

    // launch order: attn_tc is launch #6 -> captured by ncu (-s 5 -c 1)
    // 1) all input splits in one launch
    split_all<<<dim3((B_*N_*F_/4 + 255)/256, 1, 6), 256>>>(x, proj, Wq, Wk, Wv, Wo);
    // 2) xp = proj^T @ x (split-K x4)
    proj_tc<<<dim3(8, 2, B_ * KSPLIT), 256, PROJ_SMEM>>>(ph, pl, xh, xl);
    // 3) reduce partials -> xp hi/lo
    xp_reduce<<<(B_*E_*F_/4 + 255)/256, 256>>>();
    // 4) Q = 0.125 * x @ Wq^T
    tc_gemm<<<dim3(8, 128, 1), 256, TCG_SMEM>>>(
        xh, xl, wqh, wql, wqh, wql,
        nullptr, qh, ql, qh, ql, 1, 1, 0.125f);
    // 5) Kp (split bf16) ; Vp (split bf16 transposed)
    tc_gemm<<<dim3(8, 8, 2), 256, TCG_SMEM>>>(
        xph, xpl, wkh, wkl, wvh, wvl,
        nullptr, kph, kpl, vth, vtl, 2, 3, 1.f);
    // 6) persistent flash attention  (PROFILED)
    attn_tc<<<dim3(SPLIT, H_, B_), 256, ATT_SMEM>>>();
    // 7) out = ao @ Wo^T (f32)
    tc_gemm<<<dim3(8, 128, 1), 256, TCG_SMEM>>>(
        aoh, aol, woh, wol, woh, wol,
        out, nullptr, nullptr, nullptr, nullptr, 0, 0, 1.f);
}

// round 15
// speedup vs baseline: 1.0552x; 1.0552x over previous
#include <cuda_runtime.h>
#include <cuda_bf16.h>
#include <cstdint>

#define B_ 4
#define N_ 4096
#define F_ 1024
#define H_ 16
#define D_ 64
#define E_ 256
#define KSPLIT 4
#define SPLIT 2

// ---- tensor-core helpers (portable sm_80+) ----
__device__ __forceinline__ uint32_t smem_u32(const void* p) {
    uint32_t a;
    asm("{ .reg .u64 t; cvta.to.shared.u64 t, %1; cvt.u32.u64 %0, t; }" : "=r"(a) : "l"(p));
    return a;
}
__device__ __forceinline__ void ldsm4(uint32_t* r, uint32_t a) {
    asm volatile("ldmatrix.sync.aligned.m8n8.x4.shared.b16 {%0,%1,%2,%3}, [%4];"
        : "=r"(r[0]), "=r"(r[1]), "=r"(r[2]), "=r"(r[3]) : "r"(a));
}
__device__ __forceinline__ void ldsm4t(uint32_t* r, uint32_t a) {
    asm volatile("ldmatrix.sync.aligned.m8n8.x4.trans.shared.b16 {%0,%1,%2,%3}, [%4];"
        : "=r"(r[0]), "=r"(r[1]), "=r"(r[2]), "=r"(r[3]) : "r"(a));
}
__device__ __forceinline__ void mma16816(float* c, const uint32_t* a, const uint32_t* b) {
    asm volatile("mma.sync.aligned.m16n8k16.row.col.f32.bf16.bf16.f32 "
        "{%0,%1,%2,%3}, {%4,%5,%6,%7}, {%8,%9}, {%0,%1,%2,%3};"
        : "+f"(c[0]), "+f"(c[1]), "+f"(c[2]), "+f"(c[3])
        : "r"(a[0]), "r"(a[1]), "r"(a[2]), "r"(a[3]), "r"(b[0]), "r"(b[1]));
}
#define CP16(dst, src) asm volatile("cp.async.cg.shared.global [%0], [%1], 16;" :: "r"(dst), "l"(src))
#define CP_COMMIT()    asm volatile("cp.async.commit_group;" ::: "memory")
#define CP_WAIT0()     asm volatile("cp.async.wait_group 0;" ::: "memory")

__device__ __forceinline__ void split1(float v, __nv_bfloat16& h, __nv_bfloat16& l) {
    h = __float2bfloat16(v);
    l = __float2bfloat16(v - __bfloat162float(h));
}
__device__ __forceinline__ uint32_t packbf(float a, float b) {
    __nv_bfloat162 t(__float2bfloat16(a), __float2bfloat16(b));
    return *(uint32_t*)&t;
}
__device__ __forceinline__ uint32_t packbf_lo(float a, float b) {
    __nv_bfloat16 ha = __float2bfloat16(a), hb = __float2bfloat16(b);
    __nv_bfloat162 t(__float2bfloat16(a - __bfloat162float(ha)),
                     __float2bfloat16(b - __bfloat162float(hb)));
    return *(uint32_t*)&t;
}

// ---- scratch ----
__device__ float g_xpp[KSPLIT*B_*E_*F_];
__device__ __nv_bfloat16 g_xh [B_*N_*F_], g_xl [B_*N_*F_];
__device__ __nv_bfloat16 g_qh [B_*N_*F_], g_ql [B_*N_*F_];
__device__ __nv_bfloat16 g_aoh[B_*N_*F_], g_aol[B_*N_*F_];
__device__ __nv_bfloat16 g_xph[B_*E_*F_], g_xpl[B_*E_*F_];
__device__ __nv_bfloat16 g_kph[B_*E_*F_], g_kpl[B_*E_*F_];
__device__ __nv_bfloat16 g_vth[B_*F_*E_], g_vtl[B_*F_*E_];
__device__ __nv_bfloat16 g_ph [N_*E_],   g_pl [N_*E_];
__device__ __nv_bfloat16 g_wqh[F_*F_], g_wql[F_*F_];
__device__ __nv_bfloat16 g_wkh[F_*F_], g_wkl[F_*F_];
__device__ __nv_bfloat16 g_wvh[F_*F_], g_wvl[F_*F_];
__device__ __nv_bfloat16 g_woh[F_*F_], g_wol[F_*F_];

// ---------------------------------------------------------------------------
// All 6 input splits in ONE launch, FLAT block mapping (no dead blocks).
// blocks: [0,4096) x | [4096,5120) proj | then 4x1024 for Wq,Wk,Wv,Wo.
// ---------------------------------------------------------------------------
#define XBLK  (B_*N_*F_/4/256)    // 4096
#define PBLK  (N_*E_/4/256)       // 1024
#define WBLK  (F_*F_/4/256)       // 1024
#define SPLIT_BLOCKS (XBLK + PBLK + 4*WBLK)   // 9216

__global__ void __launch_bounds__(256)
split_all(const float* __restrict__ x, const float* __restrict__ proj,
          const float* __restrict__ w0, const float* __restrict__ w1,
          const float* __restrict__ w2, const float* __restrict__ w3)
{
    int bid = blockIdx.x;
    const float* in;
    __nv_bfloat16 *hi, *lo;
    int base;
    if (bid < XBLK) {
        in = x; hi = g_xh; lo = g_xl; base = bid;
    } else if (bid < XBLK + PBLK) {
        in = proj; hi = g_ph; lo = g_pl; base = bid - XBLK;
    } else {
        int wb = bid - XBLK - PBLK;
        int w = wb / WBLK;
        base = wb % WBLK;
        in = w == 0 ? w0 : w == 1 ? w1 : w == 2 ? w2 : w3;
        hi = w == 0 ? g_wqh : w == 1 ? g_wkh : w == 2 ? g_wvh : g_woh;
        lo = w == 0 ? g_wql : w == 1 ? g_wkl : w == 2 ? g_wvl : g_wol;
    }
    int i = base * 256 + threadIdx.x;
    float4 v = ((const float4*)in)[i];
    __nv_bfloat16 h0, h1, h2, h3, l0, l1, l2, l3;
    split1(v.x, h0, l0); split1(v.y, h1, l1);
    split1(v.z, h2, l2); split1(v.w, h3, l3);
    ((__nv_bfloat162*)hi)[i*2]   = __nv_bfloat162(h0, h1);
    ((__nv_bfloat162*)hi)[i*2+1] = __nv_bfloat162(h2, h3);
    ((__nv_bfloat162*)lo)[i*2]   = __nv_bfloat162(l0, l1);
    ((__nv_bfloat162*)lo)[i*2+1] = __nv_bfloat162(l2, l3);
}

#define PAD        40
#define MAT_BYTES  (128 * PAD * 2)
#define STG_BYTES  (4 * MAT_BYTES)
#define TCG_SMEM   (2 * STG_BYTES)

__device__ __forceinline__ void stage_load(
    const __nv_bfloat16* __restrict__ Ah, const __nv_bfloat16* __restrict__ Al,
    const __nv_bfloat16* __restrict__ Bh, const __nv_bfloat16* __restrict__ Bl,
    int bm, int bn, int kt, uint32_t sbase, int tid)
{
    const __nv_bfloat16* gp[4] = {
        Ah + (size_t)bm * 1024, Al + (size_t)bm * 1024,
        Bh + (size_t)bn * 1024, Bl + (size_t)bn * 1024 };
#pragma unroll
    for (int m = 0; m < 4; m++) {
        const __nv_bfloat16* base = gp[m] + kt * 32;
        uint32_t sb = sbase + m * MAT_BYTES;
#pragma unroll
        for (int it = 0; it < 2; it++) {
            int c = tid + it * 256;
            int row = c >> 2, q = c & 3;
            CP16(sb + row * (PAD * 2) + q * 16, base + (size_t)row * 1024 + q * 8);
        }
    }
}

// shared GEMM body: mainloop into acc
#define GEMM_MAINLOOP(Ah, Al, Bh, Bl, bm, bn)                                  \
    stage_load(Ah, Al, Bh, Bl, bm, bn, 0, sb, tid);                            \
    CP_COMMIT();                                                               \
    _Pragma("unroll 1")                                                        \
    for (int kt = 0; kt < 32; kt++) {                                          \
        CP_WAIT0();                                                            \
        __syncthreads();                                                       \
        if (kt + 1 < 32) {                                                     \
            stage_load(Ah, Al, Bh, Bl, bm, bn, kt + 1,                         \
                       sb + ((kt + 1) & 1) * STG_BYTES, tid);                  \
            CP_COMMIT();                                                       \
        }                                                                      \
        const uint32_t st = sb + (kt & 1) * STG_BYTES;                         \
        _Pragma("unroll")                                                      \
        for (int ks = 0; ks < 2; ks++) {                                       \
            uint32_t ah[4][4], al[4][4], bh[2][4], bl[2][4];                   \
            _Pragma("unroll")                                                  \
            for (int mt = 0; mt < 4; mt++) {                                   \
                uint32_t a = st + (wm + mt * 16 + lmA) * (PAD * 2) + lkA + ks * 32; \
                ldsm4(ah[mt], a);                                              \
                ldsm4(al[mt], a + MAT_BYTES);                                  \
            }                                                                  \
            _Pragma("unroll")                                                  \
            for (int p = 0; p < 2; p++) {                                      \
                uint32_t a = st + 2 * MAT_BYTES                                \
                           + (wn + p * 16 + rB) * (PAD * 2) + lkB + ks * 32;   \
                ldsm4(bh[p], a);                                               \
                ldsm4(bl[p], a + MAT_BYTES);                                   \
            }                                                                  \
            _Pragma("unroll")                                                  \
            for (int mt = 0; mt < 4; mt++)                                     \
                _Pragma("unroll")                                              \
                for (int nt = 0; nt < 4; nt++) {                               \
                    float* cc = acc[mt][nt];                                   \
                    const uint32_t* bhp = &bh[nt >> 1][(nt & 1) * 2];          \
                    const uint32_t* blp = &bl[nt >> 1][(nt & 1) * 2];          \
                    mma16816(cc, ah[mt], bhp);                                 \
                    mma16816(cc, ah[mt], blp);                                 \
                    mma16816(cc, al[mt], bhp);                                 \
                }                                                              \
        }                                                                      \
    }                                                                          \
    __syncthreads();

// ---------------------------------------------------------------------------
// Fused Q + Kp + Vp GEMM. grid (8, 144):
//   y in [0,128): Q tile (A=x, B=Wq, scaled split-bf16 out)
//   y in [128,136): Kp  (A=xp, B=Wk, split-bf16 out)
//   y in [136,144): Vp  (A=xp, B=Wv, split-bf16 transposed out)
// ---------------------------------------------------------------------------
__global__ void __launch_bounds__(256, 2)
qkv_gemm()
{
    extern __shared__ __nv_bfloat16 smb[];
    const uint32_t sb = smem_u32(smb);
    const int tid  = threadIdx.x;
    const int lane = tid & 31;
    const int wid  = tid >> 5;
    const int bn   = blockIdx.x * 128;
    const int y    = blockIdx.y;
    const int wm   = (wid >> 2) * 64;
    const int wn   = (wid & 3) * 32;

    const __nv_bfloat16 *Ah, *Al, *Bh, *Bl;
    __nv_bfloat16 *Ch, *Cl;
    int mode, bm;
    if (y < 128) {
        Ah = g_xh;  Al = g_xl;  Bh = g_wqh; Bl = g_wql;
        Ch = g_qh;  Cl = g_ql;  mode = 1;   bm = y * 128;
    } else if (y < 136) {
        Ah = g_xph; Al = g_xpl; Bh = g_wkh; Bl = g_wkl;
        Ch = g_kph; Cl = g_kpl; mode = 2;   bm = (y - 128) * 128;
    } else {
        Ah = g_xph; Al = g_xpl; Bh = g_wvh; Bl = g_wvl;
        Ch = g_vth; Cl = g_vtl; mode = 3;   bm = (y - 136) * 128;
    }

    float acc[4][4][4];
#pragma unroll
    for (int i = 0; i < 4; i++)
#pragma unroll
        for (int j = 0; j < 4; j++)
#pragma unroll
            for (int v = 0; v < 4; v++) acc[i][j][v] = 0.f;

    const int lmA = lane & 15;
    const int lkA = (lane >> 4) * 16;
    const int rB  = (lane & 7) + ((lane >> 4) << 3);
    const int lkB = ((lane >> 3) & 1) * 16;

    GEMM_MAINLOOP(Ah, Al, Bh, Bl, bm, bn)

    const int mr = lane >> 2, nc = (lane & 3) * 2;
#pragma unroll
    for (int mt = 0; mt < 4; mt++)
#pragma unroll
        for (int nt = 0; nt < 4; nt++) {
            int m = bm + wm + mt * 16 + mr;
            int n = bn + wn + nt * 8 + nc;
            float v00 = acc[mt][nt][0], v01 = acc[mt][nt][1];
            float v10 = acc[mt][nt][2], v11 = acc[mt][nt][3];
            if (mode == 3) {
                int b = m >> 8, e = m & 255;
                __nv_bfloat16 h, l;
                split1(v00, h, l);
                Ch[(size_t)b*F_*E_ + (size_t)n*E_ + e] = h;
                Cl[(size_t)b*F_*E_ + (size_t)n*E_ + e] = l;
                split1(v01, h, l);
                Ch[(size_t)b*F_*E_ + (size_t)(n+1)*E_ + e] = h;
                Cl[(size_t)b*F_*E_ + (size_t)(n+1)*E_ + e] = l;
                split1(v10, h, l);
                Ch[(size_t)b*F_*E_ + (size_t)n*E_ + e + 8] = h;
                Cl[(size_t)b*F_*E_ + (size_t)n*E_ + e + 8] = l;
                split1(v11, h, l);
                Ch[(size_t)b*F_*E_ + (size_t)(n+1)*E_ + e + 8] = h;
                Cl[(size_t)b*F_*E_ + (size_t)(n+1)*E_ + e + 8] = l;
            } else {
                float s = (mode == 1) ? 0.125f : 1.f;
                v00 *= s; v01 *= s; v10 *= s; v11 *= s;
                __nv_bfloat16 h0, l0, h1, l1;
                split1(v00, h0, l0); split1(v01, h1, l1);
                *(__nv_bfloat162*)&Ch[(size_t)m*1024 + n] = __nv_bfloat162(h0, h1);
                *(__nv_bfloat162*)&Cl[(size_t)m*1024 + n] = __nv_bfloat162(l0, l1);
                split1(v10, h0, l0); split1(v11, h1, l1);
                *(__nv_bfloat162*)&Ch[(size_t)(m+8)*1024 + n] = __nv_bfloat162(h0, h1);
                *(__nv_bfloat162*)&Cl[(size_t)(m+8)*1024 + n] = __nv_bfloat162(l0, l1);
            }
        }
}

// ---------------------------------------------------------------------------
// O GEMM: out = ao @ Wo^T (f32 out). grid (8, 128).
// ---------------------------------------------------------------------------
__global__ void __launch_bounds__(256, 2)
o_gemm(float* __restrict__ Cf)
{
    extern __shared__ __nv_bfloat16 smb[];
    const uint32_t sb = smem_u32(smb);
    const int tid  = threadIdx.x;
    const int lane = tid & 31;
    const int wid  = tid >> 5;
    const int bn   = blockIdx.x * 128;
    const int bm   = blockIdx.y * 128;
    const int wm   = (wid >> 2) * 64;
    const int wn   = (wid & 3) * 32;

    float acc[4][4][4];
#pragma unroll
    for (int i = 0; i < 4; i++)
#pragma unroll
        for (int j = 0; j < 4; j++)
#pragma unroll
            for (int v = 0; v < 4; v++) acc[i][j][v] = 0.f;

    const int lmA = lane & 15;
    const int lkA = (lane >> 4) * 16;
    const int rB  = (lane & 7) + ((lane >> 4) << 3);
    const int lkB = ((lane >> 3) & 1) * 16;

    GEMM_MAINLOOP(g_aoh, g_aol, g_woh, g_wol, bm, bn)

    const int mr = lane >> 2, nc = (lane & 3) * 2;
#pragma unroll
    for (int mt = 0; mt < 4; mt++)
#pragma unroll
        for (int nt = 0; nt < 4; nt++) {
            int m = bm + wm + mt * 16 + mr;
            int n = bn + wn + nt * 8 + nc;
            *(float2*)&Cf[(size_t)m * 1024 + n] =
                make_float2(acc[mt][nt][0], acc[mt][nt][1]);
            *(float2*)&Cf[(size_t)(m + 8) * 1024 + n] =
                make_float2(acc[mt][nt][2], acc[mt][nt][3]);
        }
}

// ---------------------------------------------------------------------------
// HMMA split-bf16 TN GEMM (trans ldmatrix): xp = proj^T @ x, split-K x4.
// ---------------------------------------------------------------------------
#define PPAD       136
#define PT_BYTES   (32 * PPAD * 2)
#define PSTG       (4 * PT_BYTES)
#define PROJ_SMEM  (2 * PSTG)

__device__ __forceinline__ void stage_load_p(
    const __nv_bfloat16* __restrict__ ph, const __nv_bfloat16* __restrict__ pl,
    const __nv_bfloat16* __restrict__ xh, const __nv_bfloat16* __restrict__ xl,
    int e0, int f0, int n0, uint32_t sbase, int tid)
{
    const __nv_bfloat16* gp[4] = {
        ph + (size_t)n0 * 256 + e0,  pl + (size_t)n0 * 256 + e0,
        xh + (size_t)n0 * 1024 + f0, xl + (size_t)n0 * 1024 + f0 };
    const int gs[4] = {256, 256, 1024, 1024};
#pragma unroll
    for (int m = 0; m < 4; m++) {
        uint32_t sb = sbase + m * PT_BYTES;
#pragma unroll
        for (int it = 0; it < 2; it++) {
            int c = tid + it * 256;
            int row = c >> 4, q = c & 15;
            CP16(sb + row * (PPAD * 2) + q * 16, gp[m] + (size_t)row * gs[m] + q * 8);
        }
    }
}

__global__ void __launch_bounds__(256, 2)
proj_tc(const __nv_bfloat16* __restrict__ ph, const __nv_bfloat16* __restrict__ pl,
        const __nv_bfloat16* __restrict__ xh, const __nv_bfloat16* __restrict__ xl)
{
    extern __shared__ __nv_bfloat16 smb[];
    const uint32_t sb = smem_u32(smb);
    const int tid  = threadIdx.x;
    const int lane = tid & 31;
    const int wid  = tid >> 5;
    const int f0   = blockIdx.x * 128;
    const int e0   = blockIdx.y * 128;
    const int b    = blockIdx.z >> 2;
    const int ksp  = blockIdx.z & 3;
    const int wm   = (wid >> 2) * 64;
    const int wn   = (wid & 3) * 32;
    const int nlo  = ksp * (N_ / KSPLIT);

    const __nv_bfloat16* xhb = xh + (size_t)b * N_ * F_;
    const __nv_bfloat16* xlb = xl + (size_t)b * N_ * F_;

    float acc[4][4][4];
#pragma unroll
    for (int i = 0; i < 4; i++)
#pragma unroll
        for (int j = 0; j < 4; j++)
#pragma unroll
            for (int v = 0; v < 4; v++) acc[i][j][v] = 0.f;

    const int krA = (lane & 7) + ((lane & 16) >> 1);
    const int mcA = lane & 8;
    const int krB = (lane & 7) + (lane & 8);
    const int fcB = (lane >> 4) << 3;

    stage_load_p(ph, pl, xhb, xlb, e0, f0, nlo, sb, tid);
    CP_COMMIT();

#pragma unroll 1
    for (int kt = 0; kt < 32; kt++) {
        CP_WAIT0();
        __syncthreads();
        if (kt + 1 < 32) {
            stage_load_p(ph, pl, xhb, xlb, e0, f0, nlo + (kt + 1) * 32,
                         sb + ((kt + 1) & 1) * PSTG, tid);
            CP_COMMIT();
        }

        const uint32_t st = sb + (kt & 1) * PSTG;
#pragma unroll
        for (int ks = 0; ks < 2; ks++) {
            uint32_t ah[4][4], al[4][4], bh[2][4], bl[2][4];
#pragma unroll
            for (int mt = 0; mt < 4; mt++) {
                uint32_t a = st + (ks * 16 + krA) * (PPAD * 2)
                           + (wm + mt * 16 + mcA) * 2;
                ldsm4t(ah[mt], a);
                ldsm4t(al[mt], a + PT_BYTES);
            }
#pragma unroll
            for (int p = 0; p < 2; p++) {
                uint32_t a = st + 2 * PT_BYTES + (ks * 16 + krB) * (PPAD * 2)
                           + (wn + p * 16 + fcB) * 2;
                ldsm4t(bh[p], a);
                ldsm4t(bl[p], a + PT_BYTES);
            }
#pragma unroll
            for (int mt = 0; mt < 4; mt++)
#pragma unroll
                for (int nt = 0; nt < 4; nt++) {
                    float* cc = acc[mt][nt];
                    const uint32_t* bhp = &bh[nt >> 1][(nt & 1) * 2];
                    const uint32_t* blp = &bl[nt >> 1][(nt & 1) * 2];
                    mma16816(cc, ah[mt], bhp);
                    mma16816(cc, ah[mt], blp);
                    mma16816(cc, al[mt], bhp);
                }
        }
    }
    __syncthreads();

    float* Cb = g_xpp + (size_t)ksp * (B_ * E_ * F_) + (size_t)b * E_ * F_;
    const int mr = lane >> 2, nc = (lane & 3) * 2;
#pragma unroll
    for (int mt = 0; mt < 4; mt++)
#pragma unroll
        for (int nt = 0; nt < 4; nt++) {
            int e = e0 + wm + mt * 16 + mr;
            int f = f0 + wn + nt * 8 + nc;
            *(float2*)&Cb[(size_t)e * F_ + f] =
                make_float2(acc[mt][nt][0], acc[mt][nt][1]);
            *(float2*)&Cb[(size_t)(e + 8) * F_ + f] =
                make_float2(acc[mt][nt][2], acc[mt][nt][3]);
        }
}

__global__ void __launch_bounds__(256)
xp_reduce()
{
    int i = blockIdx.x * 256 + threadIdx.x;
    const int tot = B_ * E_ * F_ / 4;
    if (i >= tot) return;
    const float4* p0 = (const float4*)g_xpp;
    float4 a = p0[i], b = p0[i + tot], c = p0[i + 2 * tot], d = p0[i + 3 * tot];
    float s[4] = {a.x + b.x + c.x + d.x, a.y + b.y + c.y + d.y,
                  a.z + b.z + c.z + d.z, a.w + b.w + c.w + d.w};
    __nv_bfloat16 h[4], l[4];
#pragma unroll
    for (int k = 0; k < 4; k++) split1(s[k], h[k], l[k]);
    ((__nv_bfloat162*)g_xph)[i*2]   = __nv_bfloat162(h[0], h[1]);
    ((__nv_bfloat162*)g_xph)[i*2+1] = __nv_bfloat162(h[2], h[3]);
    ((__nv_bfloat162*)g_xpl)[i*2]   = __nv_bfloat162(l[0], l[1]);
    ((__nv_bfloat162*)g_xpl)[i*2+1] = __nv_bfloat162(l[2], l[3]);
}

// ---------------------------------------------------------------------------
// Persistent HMMA flash attention (R13, unchanged).
// ---------------------------------------------------------------------------
#define KH_B   0
#define KL_B   36864
#define VTH_B  73728
#define VTL_B  107520
#define Q_B    141312
#define QBUF   36864
#define ATT_SMEM (Q_B + 2 * QBUF)
#define KROW   144
#define VROW   528

__device__ __forceinline__ void load_q_tile(
    uint32_t qbase, const __nv_bfloat16* qh, const __nv_bfloat16* ql,
    size_t row0, int tid)
{
    for (int c = tid; c < 1024; c += 256) {
        int q = c >> 3, k = c & 7;
        CP16(qbase + q * KROW + k * 16,          qh + (row0 + q) * F_ + k * 8);
        CP16(qbase + 18432 + q * KROW + k * 16,  ql + (row0 + q) * F_ + k * 8);
    }
}

__global__ void __launch_bounds__(256, 1)
attn_tc()
{
    extern __shared__ __nv_bfloat16 smb[];
    const uint32_t sb = smem_u32(smb);
    const int tid  = threadIdx.x;
    const int lane = tid & 31;
    const int wid  = tid >> 5;
    const int h    = blockIdx.y;
    const int b    = blockIdx.z;
    const int wq   = wid * 16;

    const __nv_bfloat16* qh = g_qh + (size_t)b * N_ * F_ + h * D_;
    const __nv_bfloat16* ql = g_ql + (size_t)b * N_ * F_ + h * D_;

    {
        const __nv_bfloat16* kh = g_kph + ((size_t)b*E_)*F_ + h*D_;
        const __nv_bfloat16* kl = g_kpl + ((size_t)b*E_)*F_ + h*D_;
        for (int c = tid; c < 2048; c += 256) {
            int e = c >> 3, q = c & 7;
            CP16(sb + KH_B + e*KROW + q*16, kh + (size_t)e*F_ + q*8);
            CP16(sb + KL_B + e*KROW + q*16, kl + (size_t)e*F_ + q*8);
        }
        const __nv_bfloat16* vh = g_vth + ((size_t)b*F_ + h*D_)*E_;
        const __nv_bfloat16* vl = g_vtl + ((size_t)b*F_ + h*D_)*E_;
        for (int c = tid; c < 2048; c += 256) {
            int dv = c >> 5, ch = c & 31;
            CP16(sb + VTH_B + dv*VROW + ch*16, vh + (size_t)dv*E_ + ch*8);
            CP16(sb + VTL_B + dv*VROW + ch*16, vl + (size_t)dv*E_ + ch*8);
        }
        load_q_tile(sb + Q_B, qh, ql, (size_t)blockIdx.x * 128, tid);
    }
    CP_COMMIT();
    CP_WAIT0();
    __syncthreads();

    const int lmA = lane & 15;
    const int lkA = (lane >> 4) * 16;
    const int rB  = (lane & 7) + ((lane >> 4) << 3);
    const int lkB = ((lane >> 3) & 1) * 16;

    int qb = 0;
#pragma unroll 1
    for (int t = blockIdx.x; t < N_ / 128; t += SPLIT) {
        const uint32_t qbase = sb + Q_B + qb * QBUF;

        float sc[32][4];
#pragma unroll
        for (int tt = 0; tt < 32; tt++)
#pragma unroll
            for (int v = 0; v < 4; v++) sc[tt][v] = 0.f;

#pragma unroll
        for (int kt = 0; kt < 4; kt++) {
            uint32_t qh4[4], ql4[4];
            {
                uint32_t a = qbase + (wq + lmA) * KROW + lkA + kt * 32;
                ldsm4(qh4, a);
                ldsm4(ql4, a + 18432);
            }
#pragma unroll
            for (int eb = 0; eb < 16; eb++) {
                uint32_t bh4[4], bl4[4];
                uint32_t a = sb + KH_B + (eb * 16 + rB) * KROW + lkB + kt * 32;
                ldsm4(bh4, a);
                ldsm4(bl4, a + (KL_B - KH_B));
#pragma unroll
                for (int half = 0; half < 2; half++) {
                    float* cc = sc[2 * eb + half];
                    const uint32_t* bhp = &bh4[half * 2];
                    const uint32_t* blp = &bl4[half * 2];
                    mma16816(cc, qh4, bhp);
                    mma16816(cc, qh4, blp);
                    mma16816(cc, ql4, bhp);
                }
            }
        }

        if (t + SPLIT < N_ / 128) {
            load_q_tile(sb + Q_B + (qb ^ 1) * QBUF, qh, ql,
                        (size_t)(t + SPLIT) * 128, tid);
            CP_COMMIT();
        }

        float mx0 = sc[0][0], mx1 = sc[0][2];
#pragma unroll
        for (int tt = 0; tt < 32; tt++) {
            mx0 = fmaxf(mx0, fmaxf(sc[tt][0], sc[tt][1]));
            mx1 = fmaxf(mx1, fmaxf(sc[tt][2], sc[tt][3]));
        }
        mx0 = fmaxf(mx0, __shfl_xor_sync(0xffffffffu, mx0, 1));
        mx0 = fmaxf(mx0, __shfl_xor_sync(0xffffffffu, mx0, 2));
        mx1 = fmaxf(mx1, __shfl_xor_sync(0xffffffffu, mx1, 1));
        mx1 = fmaxf(mx1, __shfl_xor_sync(0xffffffffu, mx1, 2));

        float s0 = 0.f, s1 = 0.f;
#pragma unroll
        for (int tt = 0; tt < 32; tt++) {
            sc[tt][0] = __expf(sc[tt][0] - mx0);
            sc[tt][1] = __expf(sc[tt][1] - mx0);
            sc[tt][2] = __expf(sc[tt][2] - mx1);
            sc[tt][3] = __expf(sc[tt][3] - mx1);
            s0 += sc[tt][0] + sc[tt][1];
            s1 += sc[tt][2] + sc[tt][3];
        }
        s0 += __shfl_xor_sync(0xffffffffu, s0, 1);
        s0 += __shfl_xor_sync(0xffffffffu, s0, 2);
        s1 += __shfl_xor_sync(0xffffffffu, s1, 1);
        s1 += __shfl_xor_sync(0xffffffffu, s1, 2);

        float o[8][4];
#pragma unroll
        for (int tt = 0; tt < 8; tt++)
#pragma unroll
            for (int v = 0; v < 4; v++) o[tt][v] = 0.f;

#pragma unroll
        for (int kt = 0; kt < 16; kt++) {
            uint32_t ph4[4], pl4[4];
            ph4[0] = packbf   (sc[2*kt][0],   sc[2*kt][1]);
            ph4[1] = packbf   (sc[2*kt][2],   sc[2*kt][3]);
            ph4[2] = packbf   (sc[2*kt+1][0], sc[2*kt+1][1]);
            ph4[3] = packbf   (sc[2*kt+1][2], sc[2*kt+1][3]);
            pl4[0] = packbf_lo(sc[2*kt][0],   sc[2*kt][1]);
            pl4[1] = packbf_lo(sc[2*kt][2],   sc[2*kt][3]);
            pl4[2] = packbf_lo(sc[2*kt+1][0], sc[2*kt+1][1]);
            pl4[3] = packbf_lo(sc[2*kt+1][2], sc[2*kt+1][3]);
#pragma unroll
            for (int pr = 0; pr < 4; pr++) {
                uint32_t vh4[4], vl4[4];
                uint32_t a = sb + VTH_B + (pr * 16 + rB) * VROW + lkB + kt * 32;
                ldsm4(vh4, a);
                ldsm4(vl4, a + (VTL_B - VTH_B));
#pragma unroll
                for (int half = 0; half < 2; half++) {
                    float* cc = o[2 * pr + half];
                    const uint32_t* bhp = &vh4[half * 2];
                    const uint32_t* blp = &vl4[half * 2];
                    mma16816(cc, ph4, bhp);
                    mma16816(cc, ph4, blp);
                    mma16816(cc, pl4, bhp);
                }
            }
        }

        const float inv0 = 1.f / s0, inv1 = 1.f / s1;
        const int row0 = b * N_ + t * 128 + wq + (lane >> 2);
        const int col0 = h * D_ + (lane & 3) * 2;
#pragma unroll
        for (int nt = 0; nt < 8; nt++) {
            float v00 = o[nt][0] * inv0, v01 = o[nt][1] * inv0;
            float v10 = o[nt][2] * inv1, v11 = o[nt][3] * inv1;
            __nv_bfloat16 h0, l0, h1, l1;
            size_t p0 = (size_t)row0 * F_ + col0 + nt * 8;
            split1(v00, h0, l0); split1(v01, h1, l1);
            *(__nv_bfloat162*)&g_aoh[p0] = __nv_bfloat162(h0, h1);
            *(__nv_bfloat162*)&g_aol[p0] = __nv_bfloat162(l0, l1);
            size_t p1 = (size_t)(row0 + 8) * F_ + col0 + nt * 8;
            split1(v10, h0, l0); split1(v11, h1, l1);
            *(__nv_bfloat162*)&g_aoh[p1] = __nv_bfloat162(h0, h1);
            *(__nv_bfloat162*)&g_aol[p1] = __nv_bfloat162(l0, l1);
        }

        CP_WAIT0();
        __syncthreads();
        qb ^= 1;
    }
}

// ---------------------------------------------------------------------------
extern "C" void kernel_launch(void* const* d_in, const int* in_sizes, int n_in,
                              void* d_out, int out_size)
{
    (void)in_sizes; (void)n_in; (void)out_size;
    const float* x    = (const float*)d_in[0];
    const float* proj = (const float*)d_in[1];
    const float* Wq   = (const float*)d_in[2];
    const float* Wk   = (const float*)d_in[3];
    const float* Wv   = (const float*)d_in[4];
    const float* Wo   = (const float*)d_in[5];
    float* out = (float*)d_out;

    __nv_bfloat16 *xh, *xl, *ph, *pl;
    cudaGetSymbolAddress((void**)&xh, g_xh);
    cudaGetSymbolAddress((void**)&xl, g_xl);
    cudaGetSymbolAddress((void**)&ph, g_ph);
    cudaGetSymbolAddress((void**)&pl, g_pl);

    cudaFuncSetAttribute(qkv_gemm,
                         cudaFuncAttributeMaxDynamicSharedMemorySize, TCG_SMEM);
    cudaFuncSetAttribute(o_gemm,
                         cudaFuncAttributeMaxDynamicSharedMemorySize, TCG_SMEM);
    cudaFuncSetAttribute(proj_tc,
                         cudaFuncAttributeMaxDynamicSharedMemorySize, PROJ_SMEM);
    cudaFuncSetAttribute(attn_tc,
                         cudaFuncAttributeMaxDynamicSharedMemorySize, ATT_SMEM);

    // 1) all input splits, flat grid (no dead blocks)
    split_all<<<SPLIT_BLOCKS, 256>>>(x, proj, Wq, Wk, Wv, Wo);
    // 2) xp = proj^T @ x (split-K x4)
    proj_tc<<<dim3(8, 2, B_ * KSPLIT), 256, PROJ_SMEM>>>(ph, pl, xh, xl);
    // 3) reduce partials -> xp hi/lo
    xp_reduce<<<(B_*E_*F_/4 + 255)/256, 256>>>();
    // 4) fused Q + Kp + Vp GEMM (Kp/Vp CTAs fill Q's scheduling tail)
    qkv_gemm<<<dim3(8, 144), 256, TCG_SMEM>>>();
    // 5) persistent flash attention
    attn_tc<<<dim3(SPLIT, H_, B_), 256, ATT_SMEM>>>();
    // 6) out = ao @ Wo^T (f32)
    o_gemm<<<dim3(8, 128), 256, TCG_SMEM>>>(out);
}

// round 16
// speedup vs baseline: 1.4553x; 1.3791x over previous
#include <cuda_runtime.h>
#include <cuda_fp16.h>
#include <cstdint>

#define B_ 4
#define N_ 4096
#define F_ 1024
#define H_ 16
#define D_ 64
#define E_ 256
#define KSPLIT 4
#define SPLIT 2

// ---- tensor-core helpers (portable sm_80+) ----
__device__ __forceinline__ uint32_t smem_u32(const void* p) {
    uint32_t a;
    asm("{ .reg .u64 t; cvta.to.shared.u64 t, %1; cvt.u32.u64 %0, t; }" : "=r"(a) : "l"(p));
    return a;
}
__device__ __forceinline__ void ldsm4(uint32_t* r, uint32_t a) {
    asm volatile("ldmatrix.sync.aligned.m8n8.x4.shared.b16 {%0,%1,%2,%3}, [%4];"
        : "=r"(r[0]), "=r"(r[1]), "=r"(r[2]), "=r"(r[3]) : "r"(a));
}
__device__ __forceinline__ void ldsm4t(uint32_t* r, uint32_t a) {
    asm volatile("ldmatrix.sync.aligned.m8n8.x4.trans.shared.b16 {%0,%1,%2,%3}, [%4];"
        : "=r"(r[0]), "=r"(r[1]), "=r"(r[2]), "=r"(r[3]) : "r"(a));
}
__device__ __forceinline__ void mma16816(float* c, const uint32_t* a, const uint32_t* b) {
    asm volatile("mma.sync.aligned.m16n8k16.row.col.f32.f16.f16.f32 "
        "{%0,%1,%2,%3}, {%4,%5,%6,%7}, {%8,%9}, {%0,%1,%2,%3};"
        : "+f"(c[0]), "+f"(c[1]), "+f"(c[2]), "+f"(c[3])
        : "r"(a[0]), "r"(a[1]), "r"(a[2]), "r"(a[3]), "r"(b[0]), "r"(b[1]));
}
#define CP16(dst, src) asm volatile("cp.async.cg.shared.global [%0], [%1], 16;" :: "r"(dst), "l"(src))
#define CP_COMMIT()    asm volatile("cp.async.commit_group;" ::: "memory")
#define CP_WAIT0()     asm volatile("cp.async.wait_group 0;" ::: "memory")

__device__ __forceinline__ void split1(float v, __half& h, __half& l) {
    h = __float2half_rn(v);
    l = __float2half_rn(v - __half2float(h));
}
__device__ __forceinline__ uint32_t packh(float a, float b) {
    __half2 t(__float2half_rn(a), __float2half_rn(b));
    return *(uint32_t*)&t;
}
__device__ __forceinline__ uint32_t packh_lo(float a, float b) {
    __half ha = __float2half_rn(a), hb = __float2half_rn(b);
    __half2 t(__float2half_rn(a - __half2float(ha)),
              __float2half_rn(b - __half2float(hb)));
    return *(uint32_t*)&t;
}

// ---- scratch (fp16; weights/K/V hi-only) ----
__device__ float g_xpp[KSPLIT*B_*E_*F_];
__device__ __half g_xh [B_*N_*F_], g_xl [B_*N_*F_];
__device__ __half g_qh [B_*N_*F_], g_ql [B_*N_*F_];
__device__ __half g_aoh[B_*N_*F_], g_aol[B_*N_*F_];
__device__ __half g_xph[B_*E_*F_], g_xpl[B_*E_*F_];
__device__ __half g_kph[B_*E_*F_];
__device__ __half g_vth[B_*F_*E_];
__device__ __half g_ph [N_*E_],   g_pl [N_*E_];
__device__ __half g_wqh[F_*F_], g_wkh[F_*F_], g_wvh[F_*F_], g_woh[F_*F_];

// ---------------------------------------------------------------------------
// All input splits in ONE flat launch. x/proj get hi+lo; weights hi only.
// ---------------------------------------------------------------------------
#define XBLK  (B_*N_*F_/4/256)    // 4096
#define PBLK  (N_*E_/4/256)       // 1024
#define WBLK  (F_*F_/4/256)       // 1024
#define SPLIT_BLOCKS (XBLK + PBLK + 4*WBLK)

__global__ void __launch_bounds__(256)
split_all(const float* __restrict__ x, const float* __restrict__ proj,
          const float* __restrict__ w0, const float* __restrict__ w1,
          const float* __restrict__ w2, const float* __restrict__ w3)
{
    int bid = blockIdx.x;
    if (bid < XBLK + PBLK) {
        const float* in; __half *hi, *lo; int base;
        if (bid < XBLK) { in = x; hi = g_xh; lo = g_xl; base = bid; }
        else            { in = proj; hi = g_ph; lo = g_pl; base = bid - XBLK; }
        int i = base * 256 + threadIdx.x;
        float4 v = ((const float4*)in)[i];
        __half h0, h1, h2, h3, l0, l1, l2, l3;
        split1(v.x, h0, l0); split1(v.y, h1, l1);
        split1(v.z, h2, l2); split1(v.w, h3, l3);
        ((__half2*)hi)[i*2]   = __half2(h0, h1);
        ((__half2*)hi)[i*2+1] = __half2(h2, h3);
        ((__half2*)lo)[i*2]   = __half2(l0, l1);
        ((__half2*)lo)[i*2+1] = __half2(l2, l3);
    } else {
        int wb = bid - XBLK - PBLK;
        int w = wb / WBLK;
        int base = wb % WBLK;
        const float* in = w == 0 ? w0 : w == 1 ? w1 : w == 2 ? w2 : w3;
        __half* hi = w == 0 ? g_wqh : w == 1 ? g_wkh : w == 2 ? g_wvh : g_woh;
        int i = base * 256 + threadIdx.x;
        float4 v = ((const float4*)in)[i];
        ((__half2*)hi)[i*2]   = __half2(__float2half_rn(v.x), __float2half_rn(v.y));
        ((__half2*)hi)[i*2+1] = __half2(__float2half_rn(v.z), __float2half_rn(v.w));
    }
}

#define PAD        40
#define MAT_BYTES  (128 * PAD * 2)
#define STG_BYTES  (3 * MAT_BYTES)      // Ah, Al, Bh
#define TCG_SMEM   (2 * STG_BYTES)      // 61440

__device__ __forceinline__ void stage_load(
    const __half* __restrict__ Ah, const __half* __restrict__ Al,
    const __half* __restrict__ Bh,
    int bm, int bn, int kt, uint32_t sbase, int tid)
{
    const __half* gp[3] = {
        Ah + (size_t)bm * 1024, Al + (size_t)bm * 1024, Bh + (size_t)bn * 1024 };
#pragma unroll
    for (int m = 0; m < 3; m++) {
        const __half* base = gp[m] + kt * 32;
        uint32_t sb = sbase + m * MAT_BYTES;
#pragma unroll
        for (int it = 0; it < 2; it++) {
            int c = tid + it * 256;
            int row = c >> 2, q = c & 3;
            CP16(sb + row * (PAD * 2) + q * 16, base + (size_t)row * 1024 + q * 8);
        }
    }
}

// shared GEMM mainloop (2-product: a_hi*b_hi + a_lo*b_hi)
#define GEMM_MAINLOOP(Ah, Al, Bh, bm, bn)                                      \
    stage_load(Ah, Al, Bh, bm, bn, 0, sb, tid);                                \
    CP_COMMIT();                                                               \
    _Pragma("unroll 1")                                                        \
    for (int kt = 0; kt < 32; kt++) {                                          \
        CP_WAIT0();                                                            \
        __syncthreads();                                                       \
        if (kt + 1 < 32) {                                                     \
            stage_load(Ah, Al, Bh, bm, bn, kt + 1,                             \
                       sb + ((kt + 1) & 1) * STG_BYTES, tid);                  \
            CP_COMMIT();                                                       \
        }                                                                      \
        const uint32_t st = sb + (kt & 1) * STG_BYTES;                         \
        _Pragma("unroll")                                                      \
        for (int ks = 0; ks < 2; ks++) {                                       \
            uint32_t ah[4][4], al[4][4], bh[2][4];                             \
            _Pragma("unroll")                                                  \
            for (int mt = 0; mt < 4; mt++) {                                   \
                uint32_t a = st + (wm + mt * 16 + lmA) * (PAD * 2) + lkA + ks * 32; \
                ldsm4(ah[mt], a);                                              \
                ldsm4(al[mt], a + MAT_BYTES);                                  \
            }                                                                  \
            _Pragma("unroll")                                                  \
            for (int p = 0; p < 2; p++) {                                      \
                uint32_t a = st + 2 * MAT_BYTES                                \
                           + (wn + p * 16 + rB) * (PAD * 2) + lkB + ks * 32;   \
                ldsm4(bh[p], a);                                               \
            }                                                                  \
            _Pragma("unroll")                                                  \
            for (int mt = 0; mt < 4; mt++)                                     \
                _Pragma("unroll")                                              \
                for (int nt = 0; nt < 4; nt++) {                               \
                    float* cc = acc[mt][nt];                                   \
                    const uint32_t* bhp = &bh[nt >> 1][(nt & 1) * 2];          \
                    mma16816(cc, ah[mt], bhp);                                 \
                    mma16816(cc, al[mt], bhp);                                 \
                }                                                              \
        }                                                                      \
    }                                                                          \
    __syncthreads();

// ---------------------------------------------------------------------------
// Fused Q + Kp + Vp GEMM. grid (8, 144).
// ---------------------------------------------------------------------------
__global__ void __launch_bounds__(256, 2)
qkv_gemm()
{
    extern __shared__ __half smb[];
    const uint32_t sb = smem_u32(smb);
    const int tid  = threadIdx.x;
    const int lane = tid & 31;
    const int wid  = tid >> 5;
    const int bn   = blockIdx.x * 128;
    const int y    = blockIdx.y;
    const int wm   = (wid >> 2) * 64;
    const int wn   = (wid & 3) * 32;

    const __half *Ah, *Al, *Bh;
    int mode, bm;
    if (y < 128) {
        Ah = g_xh;  Al = g_xl;  Bh = g_wqh; mode = 1; bm = y * 128;
    } else if (y < 136) {
        Ah = g_xph; Al = g_xpl; Bh = g_wkh; mode = 2; bm = (y - 128) * 128;
    } else {
        Ah = g_xph; Al = g_xpl; Bh = g_wvh; mode = 3; bm = (y - 136) * 128;
    }

    float acc[4][4][4];
#pragma unroll
    for (int i = 0; i < 4; i++)
#pragma unroll
        for (int j = 0; j < 4; j++)
#pragma unroll
            for (int v = 0; v < 4; v++) acc[i][j][v] = 0.f;

    const int lmA = lane & 15;
    const int lkA = (lane >> 4) * 16;
    const int rB  = (lane & 7) + ((lane >> 4) << 3);
    const int lkB = ((lane >> 3) & 1) * 16;

    GEMM_MAINLOOP(Ah, Al, Bh, bm, bn)

    const int mr = lane >> 2, nc = (lane & 3) * 2;
#pragma unroll
    for (int mt = 0; mt < 4; mt++)
#pragma unroll
        for (int nt = 0; nt < 4; nt++) {
            int m = bm + wm + mt * 16 + mr;
            int n = bn + wn + nt * 8 + nc;
            float v00 = acc[mt][nt][0], v01 = acc[mt][nt][1];
            float v10 = acc[mt][nt][2], v11 = acc[mt][nt][3];
            if (mode == 1) {
                v00 *= 0.125f; v01 *= 0.125f; v10 *= 0.125f; v11 *= 0.125f;
                __half h0, l0, h1, l1;
                split1(v00, h0, l0); split1(v01, h1, l1);
                *(__half2*)&g_qh[(size_t)m*1024 + n] = __half2(h0, h1);
                *(__half2*)&g_ql[(size_t)m*1024 + n] = __half2(l0, l1);
                split1(v10, h0, l0); split1(v11, h1, l1);
                *(__half2*)&g_qh[(size_t)(m+8)*1024 + n] = __half2(h0, h1);
                *(__half2*)&g_ql[(size_t)(m+8)*1024 + n] = __half2(l0, l1);
            } else if (mode == 2) {
                *(__half2*)&g_kph[(size_t)m*1024 + n] =
                    __half2(__float2half_rn(v00), __float2half_rn(v01));
                *(__half2*)&g_kph[(size_t)(m+8)*1024 + n] =
                    __half2(__float2half_rn(v10), __float2half_rn(v11));
            } else {
                int b = m >> 8, e = m & 255;
                g_vth[(size_t)b*F_*E_ + (size_t)n*E_ + e]         = __float2half_rn(v00);
                g_vth[(size_t)b*F_*E_ + (size_t)(n+1)*E_ + e]     = __float2half_rn(v01);
                g_vth[(size_t)b*F_*E_ + (size_t)n*E_ + e + 8]     = __float2half_rn(v10);
                g_vth[(size_t)b*F_*E_ + (size_t)(n+1)*E_ + e + 8] = __float2half_rn(v11);
            }
        }
}

// ---------------------------------------------------------------------------
// O GEMM: out = ao @ Wo^T (f32 out). grid (8, 128).
// ---------------------------------------------------------------------------
__global__ void __launch_bounds__(256, 2)
o_gemm(float* __restrict__ Cf)
{
    extern __shared__ __half smb[];
    const uint32_t sb = smem_u32(smb);
    const int tid  = threadIdx.x;
    const int lane = tid & 31;
    const int wid  = tid >> 5;
    const int bn   = blockIdx.x * 128;
    const int bm   = blockIdx.y * 128;
    const int wm   = (wid >> 2) * 64;
    const int wn   = (wid & 3) * 32;

    float acc[4][4][4];
#pragma unroll
    for (int i = 0; i < 4; i++)
#pragma unroll
        for (int j = 0; j < 4; j++)
#pragma unroll
            for (int v = 0; v < 4; v++) acc[i][j][v] = 0.f;

    const int lmA = lane & 15;
    const int lkA = (lane >> 4) * 16;
    const int rB  = (lane & 7) + ((lane >> 4) << 3);
    const int lkB = ((lane >> 3) & 1) * 16;

    GEMM_MAINLOOP(g_aoh, g_aol, g_woh, bm, bn)

    const int mr = lane >> 2, nc = (lane & 3) * 2;
#pragma unroll
    for (int mt = 0; mt < 4; mt++)
#pragma unroll
        for (int nt = 0; nt < 4; nt++) {
            int m = bm + wm + mt * 16 + mr;
            int n = bn + wn + nt * 8 + nc;
            *(float2*)&Cf[(size_t)m * 1024 + n] =
                make_float2(acc[mt][nt][0], acc[mt][nt][1]);
            *(float2*)&Cf[(size_t)(m + 8) * 1024 + n] =
                make_float2(acc[mt][nt][2], acc[mt][nt][3]);
        }
}

// ---------------------------------------------------------------------------
// TN GEMM (trans ldmatrix): xp = proj^T @ x, split-K x4.
// A = proj (hi/lo), B = x (hi only).
// ---------------------------------------------------------------------------
#define PPAD       136
#define PT_BYTES   (32 * PPAD * 2)
#define PSTG       (3 * PT_BYTES)
#define PROJ_SMEM  (2 * PSTG)

__device__ __forceinline__ void stage_load_p(
    const __half* __restrict__ ph, const __half* __restrict__ pl,
    const __half* __restrict__ xh,
    int e0, int f0, int n0, uint32_t sbase, int tid)
{
    const __half* gp[3] = {
        ph + (size_t)n0 * 256 + e0, pl + (size_t)n0 * 256 + e0,
        xh + (size_t)n0 * 1024 + f0 };
    const int gs[3] = {256, 256, 1024};
#pragma unroll
    for (int m = 0; m < 3; m++) {
        uint32_t sb = sbase + m * PT_BYTES;
#pragma unroll
        for (int it = 0; it < 2; it++) {
            int c = tid + it * 256;
            int row = c >> 4, q = c & 15;
            CP16(sb + row * (PPAD * 2) + q * 16, gp[m] + (size_t)row * gs[m] + q * 8);
        }
    }
}

__global__ void __launch_bounds__(256, 2)
proj_tc(const __half* __restrict__ ph, const __half* __restrict__ pl,
        const __half* __restrict__ xh)
{
    extern __shared__ __half smb[];
    const uint32_t sb = smem_u32(smb);
    const int tid  = threadIdx.x;
    const int lane = tid & 31;
    const int wid  = tid >> 5;
    const int f0   = blockIdx.x * 128;
    const int e0   = blockIdx.y * 128;
    const int b    = blockIdx.z >> 2;
    const int ksp  = blockIdx.z & 3;
    const int wm   = (wid >> 2) * 64;
    const int wn   = (wid & 3) * 32;
    const int nlo  = ksp * (N_ / KSPLIT);

    const __half* xhb = xh + (size_t)b * N_ * F_;

    float acc[4][4][4];
#pragma unroll
    for (int i = 0; i < 4; i++)
#pragma unroll
        for (int j = 0; j < 4; j++)
#pragma unroll
            for (int v = 0; v < 4; v++) acc[i][j][v] = 0.f;

    const int krA = (lane & 7) + ((lane & 16) >> 1);
    const int mcA = lane & 8;
    const int krB = (lane & 7) + (lane & 8);
    const int fcB = (lane >> 4) << 3;

    stage_load_p(ph, pl, xhb, e0, f0, nlo, sb, tid);
    CP_COMMIT();

#pragma unroll 1
    for (int kt = 0; kt < 32; kt++) {
        CP_WAIT0();
        __syncthreads();
        if (kt + 1 < 32) {
            stage_load_p(ph, pl, xhb, e0, f0, nlo + (kt + 1) * 32,
                         sb + ((kt + 1) & 1) * PSTG, tid);
            CP_COMMIT();
        }

        const uint32_t st = sb + (kt & 1) * PSTG;
#pragma unroll
        for (int ks = 0; ks < 2; ks++) {
            uint32_t ah[4][4], al[4][4], bh[2][4];
#pragma unroll
            for (int mt = 0; mt < 4; mt++) {
                uint32_t a = st + (ks * 16 + krA) * (PPAD * 2)
                           + (wm + mt * 16 + mcA) * 2;
                ldsm4t(ah[mt], a);
                ldsm4t(al[mt], a + PT_BYTES);
            }
#pragma unroll
            for (int p = 0; p < 2; p++) {
                uint32_t a = st + 2 * PT_BYTES + (ks * 16 + krB) * (PPAD * 2)
                           + (wn + p * 16 + fcB) * 2;
                ldsm4t(bh[p], a);
            }
#pragma unroll
            for (int mt = 0; mt < 4; mt++)
#pragma unroll
                for (int nt = 0; nt < 4; nt++) {
                    float* cc = acc[mt][nt];
                    const uint32_t* bhp = &bh[nt >> 1][(nt & 1) * 2];
                    mma16816(cc, ah[mt], bhp);
                    mma16816(cc, al[mt], bhp);
                }
        }
    }
    __syncthreads();

    float* Cb = g_xpp + (size_t)ksp * (B_ * E_ * F_) + (size_t)b * E_ * F_;
    const int mr = lane >> 2, nc = (lane & 3) * 2;
#pragma unroll
    for (int mt = 0; mt < 4; mt++)
#pragma unroll
        for (int nt = 0; nt < 4; nt++) {
            int e = e0 + wm + mt * 16 + mr;
            int f = f0 + wn + nt * 8 + nc;
            *(float2*)&Cb[(size_t)e * F_ + f] =
                make_float2(acc[mt][nt][0], acc[mt][nt][1]);
            *(float2*)&Cb[(size_t)(e + 8) * F_ + f] =
                make_float2(acc[mt][nt][2], acc[mt][nt][3]);
        }
}

__global__ void __launch_bounds__(256)
xp_reduce()
{
    int i = blockIdx.x * 256 + threadIdx.x;
    const int tot = B_ * E_ * F_ / 4;
    if (i >= tot) return;
    const float4* p0 = (const float4*)g_xpp;
    float4 a = p0[i], b = p0[i + tot], c = p0[i + 2 * tot], d = p0[i + 3 * tot];
    float s[4] = {a.x + b.x + c.x + d.x, a.y + b.y + c.y + d.y,
                  a.z + b.z + c.z + d.z, a.w + b.w + c.w + d.w};
    __half h[4], l[4];
#pragma unroll
    for (int k = 0; k < 4; k++) split1(s[k], h[k], l[k]);
    ((__half2*)g_xph)[i*2]   = __half2(h[0], h[1]);
    ((__half2*)g_xph)[i*2+1] = __half2(h[2], h[3]);
    ((__half2*)g_xpl)[i*2]   = __half2(l[0], l[1]);
    ((__half2*)g_xpl)[i*2+1] = __half2(l[2], l[3]);
}

// ---------------------------------------------------------------------------
// Persistent flash attention (fp16 2-product). K/V hi only; Q hi/lo.
// smem: K 36864 + Vt 33792 + Q 2 x 36864 = 144384 B.
// ---------------------------------------------------------------------------
#define KH_B   0
#define VTH_B  36864
#define Q_B    70656
#define QBUF   36864
#define ATT_SMEM (Q_B + 2 * QBUF)    // 144384
#define KROW   144
#define VROW   528

__device__ __forceinline__ void load_q_tile(
    uint32_t qbase, const __half* qh, const __half* ql, size_t row0, int tid)
{
    for (int c = tid; c < 1024; c += 256) {
        int q = c >> 3, k = c & 7;
        CP16(qbase + q * KROW + k * 16,          qh + (row0 + q) * F_ + k * 8);
        CP16(qbase + 18432 + q * KROW + k * 16,  ql + (row0 + q) * F_ + k * 8);
    }
}

__global__ void __launch_bounds__(256, 1)
attn_tc()
{
    extern __shared__ __half smb[];
    const uint32_t sb = smem_u32(smb);
    const int tid  = threadIdx.x;
    const int lane = tid & 31;
    const int wid  = tid >> 5;
    const int h    = blockIdx.y;
    const int b    = blockIdx.z;
    const int wq   = wid * 16;

    const __half* qh = g_qh + (size_t)b * N_ * F_ + h * D_;
    const __half* ql = g_ql + (size_t)b * N_ * F_ + h * D_;

    {
        const __half* kh = g_kph + ((size_t)b*E_)*F_ + h*D_;
        for (int c = tid; c < 2048; c += 256) {
            int e = c >> 3, q = c & 7;
            CP16(sb + KH_B + e*KROW + q*16, kh + (size_t)e*F_ + q*8);
        }
        const __half* vh = g_vth + ((size_t)b*F_ + h*D_)*E_;
        for (int c = tid; c < 2048; c += 256) {
            int dv = c >> 5, ch = c & 31;
            CP16(sb + VTH_B + dv*VROW + ch*16, vh + (size_t)dv*E_ + ch*8);
        }
        load_q_tile(sb + Q_B, qh, ql, (size_t)blockIdx.x * 128, tid);
    }
    CP_COMMIT();
    CP_WAIT0();
    __syncthreads();

    const int lmA = lane & 15;
    const int lkA = (lane >> 4) * 16;
    const int rB  = (lane & 7) + ((lane >> 4) << 3);
    const int lkB = ((lane >> 3) & 1) * 16;

    int qb = 0;
#pragma unroll 1
    for (int t = blockIdx.x; t < N_ / 128; t += SPLIT) {
        const uint32_t qbase = sb + Q_B + qb * QBUF;

        float sc[32][4];
#pragma unroll
        for (int tt = 0; tt < 32; tt++)
#pragma unroll
            for (int v = 0; v < 4; v++) sc[tt][v] = 0.f;

#pragma unroll
        for (int kt = 0; kt < 4; kt++) {
            uint32_t qh4[4], ql4[4];
            {
                uint32_t a = qbase + (wq + lmA) * KROW + lkA + kt * 32;
                ldsm4(qh4, a);
                ldsm4(ql4, a + 18432);
            }
#pragma unroll
            for (int eb = 0; eb < 16; eb++) {
                uint32_t bh4[4];
                uint32_t a = sb + KH_B + (eb * 16 + rB) * KROW + lkB + kt * 32;
                ldsm4(bh4, a);
#pragma unroll
                for (int half = 0; half < 2; half++) {
                    float* cc = sc[2 * eb + half];
                    const uint32_t* bhp = &bh4[half * 2];
                    mma16816(cc, qh4, bhp);
                    mma16816(cc, ql4, bhp);
                }
            }
        }

        if (t + SPLIT < N_ / 128) {
            load_q_tile(sb + Q_B + (qb ^ 1) * QBUF, qh, ql,
                        (size_t)(t + SPLIT) * 128, tid);
            CP_COMMIT();
        }

        float mx0 = sc[0][0], mx1 = sc[0][2];
#pragma unroll
        for (int tt = 0; tt < 32; tt++) {
            mx0 = fmaxf(mx0, fmaxf(sc[tt][0], sc[tt][1]));
            mx1 = fmaxf(mx1, fmaxf(sc[tt][2], sc[tt][3]));
        }
        mx0 = fmaxf(mx0, __shfl_xor_sync(0xffffffffu, mx0, 1));
        mx0 = fmaxf(mx0, __shfl_xor_sync(0xffffffffu, mx0, 2));
        mx1 = fmaxf(mx1, __shfl_xor_sync(0xffffffffu, mx1, 1));
        mx1 = fmaxf(mx1, __shfl_xor_sync(0xffffffffu, mx1, 2));

        float s0 = 0.f, s1 = 0.f;
#pragma unroll
        for (int tt = 0; tt < 32; tt++) {
            sc[tt][0] = __expf(sc[tt][0] - mx0);
            sc[tt][1] = __expf(sc[tt][1] - mx0);
            sc[tt][2] = __expf(sc[tt][2] - mx1);
            sc[tt][3] = __expf(sc[tt][3] - mx1);
            s0 += sc[tt][0] + sc[tt][1];
            s1 += sc[tt][2] + sc[tt][3];
        }
        s0 += __shfl_xor_sync(0xffffffffu, s0, 1);
        s0 += __shfl_xor_sync(0xffffffffu, s0, 2);
        s1 += __shfl_xor_sync(0xffffffffu, s1, 1);
        s1 += __shfl_xor_sync(0xffffffffu, s1, 2);

        float o[8][4];
#pragma unroll
        for (int tt = 0; tt < 8; tt++)
#pragma unroll
            for (int v = 0; v < 4; v++) o[tt][v] = 0.f;

#pragma unroll
        for (int kt = 0; kt < 16; kt++) {
            uint32_t ph4[4], pl4[4];
            ph4[0] = packh   (sc[2*kt][0],   sc[2*kt][1]);
            ph4[1] = packh   (sc[2*kt][2],   sc[2*kt][3]);
            ph4[2] = packh   (sc[2*kt+1][0], sc[2*kt+1][1]);
            ph4[3] = packh   (sc[2*kt+1][2], sc[2*kt+1][3]);
            pl4[0] = packh_lo(sc[2*kt][0],   sc[2*kt][1]);
            pl4[1] = packh_lo(sc[2*kt][2],   sc[2*kt][3]);
            pl4[2] = packh_lo(sc[2*kt+1][0], sc[2*kt+1][1]);
            pl4[3] = packh_lo(sc[2*kt+1][2], sc[2*kt+1][3]);
#pragma unroll
            for (int pr = 0; pr < 4; pr++) {
                uint32_t vh4[4];
                uint32_t a = sb + VTH_B + (pr * 16 + rB) * VROW + lkB + kt * 32;
                ldsm4(vh4, a);
#pragma unroll
                for (int half = 0; half < 2; half++) {
                    float* cc = o[2 * pr + half];
                    const uint32_t* bhp = &vh4[half * 2];
                    mma16816(cc, ph4, bhp);
                    mma16816(cc, pl4, bhp);
                }
            }
        }

        const float inv0 = 1.f / s0, inv1 = 1.f / s1;
        const int row0 = b * N_ + t * 128 + wq + (lane >> 2);
        const int col0 = h * D_ + (lane & 3) * 2;
#pragma unroll
        for (int nt = 0; nt < 8; nt++) {
            float v00 = o[nt][0] * inv0, v01 = o[nt][1] * inv0;
            float v10 = o[nt][2] * inv1, v11 = o[nt][3] * inv1;
            __half h0, l0, h1, l1;
            size_t p0 = (size_t)row0 * F_ + col0 + nt * 8;
            split1(v00, h0, l0); split1(v01, h1, l1);
            *(__half2*)&g_aoh[p0] = __half2(h0, h1);
            *(__half2*)&g_aol[p0] = __half2(l0, l1);
            size_t p1 = (size_t)(row0 + 8) * F_ + col0 + nt * 8;
            split1(v10, h0, l0); split1(v11, h1, l1);
            *(__half2*)&g_aoh[p1] = __half2(h0, h1);
            *(__half2*)&g_aol[p1] = __half2(l0, l1);
        }

        CP_WAIT0();
        __syncthreads();
        qb ^= 1;
    }
}

// ---------------------------------------------------------------------------
extern "C" void kernel_launch(void* const* d_in, const int* in_sizes, int n_in,
                              void* d_out, int out_size)
{
    (void)in_sizes; (void)n_in; (void)out_size;
    const float* x    = (const float*)d_in[0];
    const float* proj = (const float*)d_in[1];
    const float* Wq   = (const float*)d_in[2];
    const float* Wk   = (const float*)d_in[3];
    const float* Wv   = (const float*)d_in[4];
    const float* Wo   = (const float*)d_in[5];
    float* out = (float*)d_out;

    __half *xh, *ph, *pl;
    cudaGetSymbolAddress((void**)&xh, g_xh);
    cudaGetSymbolAddress((void**)&ph, g_ph);
    cudaGetSymbolAddress((void**)&pl, g_pl);

    cudaFuncSetAttribute(qkv_gemm,
                         cudaFuncAttributeMaxDynamicSharedMemorySize, TCG_SMEM);
    cudaFuncSetAttribute(o_gemm,
                         cudaFuncAttributeMaxDynamicSharedMemorySize, TCG_SMEM);
    cudaFuncSetAttribute(proj_tc,
                         cudaFuncAttributeMaxDynamicSharedMemorySize, PROJ_SMEM);
    cudaFuncSetAttribute(attn_tc,
                         cudaFuncAttributeMaxDynamicSharedMemorySize, ATT_SMEM);

    // 1) input splits (flat grid)
    split_all<<<SPLIT_BLOCKS, 256>>>(x, proj, Wq, Wk, Wv, Wo);
    // 2) xp = proj^T @ x (split-K x4)
    proj_tc<<<dim3(8, 2, B_ * KSPLIT), 256, PROJ_SMEM>>>(ph, pl, xh);
    // 3) reduce partials -> xp hi/lo
    xp_reduce<<<(B_*E_*F_/4 + 255)/256, 256>>>();
    // 4) fused Q + Kp + Vp GEMM
    qkv_gemm<<<dim3(8, 144), 256, TCG_SMEM>>>();
    // 5) persistent flash attention
    attn_tc<<<dim3(SPLIT, H_, B_), 256, ATT_SMEM>>>();
    // 6) out = ao @ Wo^T (f32)
    o_gemm<<<dim3(8, 128), 256, TCG_SMEM>>>(out);
}